// round 6
// baseline (speedup 1.0000x reference)
#include <cuda_runtime.h>
#include <math.h>

// TV loss over x:(3, 4096, 4096) fp32 -> scalar sqrt(sum(dx^2)+sum(dy^2))
// Single fused kernel, 2-row unrolled mainloop for MLP, 1536 blocks for occupancy.

#define W 4096
#define H 4096
#define CH 3
#define ROWS_PER_BLOCK 32
#define THREADS 256            // 256 threads * 4 floats = 1024 columns per block

#define GRID_X (W / (THREADS * 4))                              // 4
#define GRID_Y ((H - 1 + ROWS_PER_BLOCK - 1) / ROWS_PER_BLOCK)  // 128
#define NUM_BLOCKS (GRID_X * GRID_Y * CH)                       // 1536

__device__ unsigned long long g_acc_bits = 0ull;   // double accumulator as bits
__device__ unsigned int g_count = 0;

// accumulate dx^2 (within-row) + dy^2 (cur vs nxt) for 4 columns
__device__ __forceinline__ void tv_accum(float& acc, const float4& cur, float curext,
                                         const float4& nxt, bool last_col) {
    float d0 = cur.y - cur.x;
    float d1 = cur.z - cur.y;
    float d2 = cur.w - cur.z;
    acc = fmaf(d0, d0, acc);
    acc = fmaf(d1, d1, acc);
    acc = fmaf(d2, d2, acc);
    float e0 = nxt.x - cur.x;
    float e1 = nxt.y - cur.y;
    float e2 = nxt.z - cur.z;
    acc = fmaf(e0, e0, acc);
    acc = fmaf(e1, e1, acc);
    acc = fmaf(e2, e2, acc);
    if (!last_col) {
        float d3 = curext - cur.w;
        float e3 = nxt.w - cur.w;
        acc = fmaf(d3, d3, acc);
        acc = fmaf(e3, e3, acc);
    }
}

__global__ __launch_bounds__(THREADS) void tv_fused_kernel(const float* __restrict__ x,
                                                           float* __restrict__ out) {
    const int ch   = blockIdx.z;
    const int c4   = (blockIdx.x * THREADS + threadIdx.x) * 4;
    const int row0 = blockIdx.y * ROWS_PER_BLOCK;

    const float* __restrict__ base = x + (size_t)ch * W * H;

    int rend = row0 + ROWS_PER_BLOCK;
    if (rend > H - 1) rend = H - 1;     // last valid base row is H-2 = 4094

    const bool last_col = (c4 == W - 4);  // j=4095 excluded entirely

    float acc = 0.0f;

    const float* p = base + (size_t)row0 * W + c4;
    float4 cur    = *(const float4*)p;
    float  curext = last_col ? 0.0f : p[4];

    // ---- 2-row unrolled mainloop: both loads issued before any use ----
    int i = row0;
    const int npair_end = row0 + ((rend - row0) & ~1);
    for (; i < npair_end; i += 2) {
        const float* p1 = base + (size_t)(i + 1) * W + c4;
        const float* p2 = base + (size_t)(i + 2) * W + c4;
        float4 n1 = *(const float4*)p1;
        float4 n2 = *(const float4*)p2;
        float n1ext = last_col ? 0.0f : p1[4];
        float n2ext = last_col ? 0.0f : p2[4];

        tv_accum(acc, cur, curext, n1, last_col);
        tv_accum(acc, n1, n1ext, n2, last_col);

        cur = n2;
        curext = n2ext;
    }
    if (i < rend) {   // odd trailing row (only the last block row: 31 rows)
        const float* p1 = base + (size_t)(i + 1) * W + c4;
        float4 n1 = *(const float4*)p1;
        tv_accum(acc, cur, curext, n1, last_col);
    }

    // ---- block reduction ----
    #pragma unroll
    for (int off = 16; off > 0; off >>= 1)
        acc += __shfl_down_sync(0xFFFFFFFFu, acc, off);

    __shared__ float warp_sums[THREADS / 32];
    __shared__ bool is_last;
    const int lane = threadIdx.x & 31;
    const int wid  = threadIdx.x >> 5;
    if (lane == 0) warp_sums[wid] = acc;
    __syncthreads();

    if (wid == 0) {
        float v = (lane < THREADS / 32) ? warp_sums[lane] : 0.0f;
        #pragma unroll
        for (int off = 4; off > 0; off >>= 1)
            v += __shfl_down_sync(0xFFFFFFFFu, v, off);
        if (lane == 0) {
            atomicAdd((double*)&g_acc_bits, (double)v);
            __threadfence();
            unsigned int ticket = atomicInc(&g_count, NUM_BLOCKS - 1);
            is_last = (ticket == NUM_BLOCKS - 1);   // wraps back to 0 for next replay
        }
    }
    __syncthreads();

    // Last block finalizes: read+reset accumulator, write sqrt.
    if (is_last && threadIdx.x == 0) {
        unsigned long long bits = atomicExch(&g_acc_bits, 0ull);
        double total = __longlong_as_double(bits);
        out[0] = (float)sqrt(total);
    }
}

extern "C" void kernel_launch(void* const* d_in, const int* in_sizes, int n_in,
                              void* d_out, int out_size) {
    const float* x = (const float*)d_in[0];
    float* out = (float*)d_out;

    dim3 grid(GRID_X, GRID_Y, CH);
    tv_fused_kernel<<<grid, THREADS>>>(x, out);
}

// round 7
// speedup vs baseline: 1.0723x; 1.0723x over previous
#include <cuda_runtime.h>
#include <math.h>

// TV loss over x:(3, 4096, 4096) fp32 -> scalar sqrt(sum(dx^2)+sum(dy^2))
// Single fused kernel, single full wave (1176 blocks <= 148 SMs * 8 blocks),
// balanced computed row ranges, 2-row unrolled mainloop.

#define W 4096
#define H 4096
#define CH 3
#define THREADS 256            // 256 threads * 4 floats = 1024 columns per block
#define GRID_X (W / (THREADS * 4))   // 4 column stripes
#define NGROUPS 98                   // row groups: 4*98*3 = 1176 blocks (<=1184 = one wave)
#define NUM_BLOCKS (GRID_X * NGROUPS * CH)

#define BASE_ROWS (H - 1)            // 4095 base rows (rows 0..4094)

__device__ unsigned long long g_acc_bits = 0ull;   // double accumulator as bits
__device__ unsigned int g_count = 0;

// accumulate dx^2 (within-row) + dy^2 (cur vs nxt) for this thread's 4 columns
__device__ __forceinline__ void tv_accum(float& acc, const float4& cur, float curext,
                                         const float4& nxt, bool last_col) {
    float d0 = cur.y - cur.x;
    float d1 = cur.z - cur.y;
    float d2 = cur.w - cur.z;
    acc = fmaf(d0, d0, acc);
    acc = fmaf(d1, d1, acc);
    acc = fmaf(d2, d2, acc);
    float e0 = nxt.x - cur.x;
    float e1 = nxt.y - cur.y;
    float e2 = nxt.z - cur.z;
    acc = fmaf(e0, e0, acc);
    acc = fmaf(e1, e1, acc);
    acc = fmaf(e2, e2, acc);
    if (!last_col) {
        float d3 = curext - cur.w;
        float e3 = nxt.w - cur.w;
        acc = fmaf(d3, d3, acc);
        acc = fmaf(e3, e3, acc);
    }
}

__global__ __launch_bounds__(THREADS, 8) void tv_fused_kernel(const float* __restrict__ x,
                                                              float* __restrict__ out) {
    const int ch  = blockIdx.z;
    const int c4  = (blockIdx.x * THREADS + threadIdx.x) * 4;
    const int g   = blockIdx.y;

    // balanced row range: group g covers base rows [row0, rend)
    const int row0 = (int)(((long long)g * BASE_ROWS) / NGROUPS);
    const int rend = (int)(((long long)(g + 1) * BASE_ROWS) / NGROUPS);

    const float* __restrict__ base = x + (size_t)ch * W * H;
    const bool last_col = (c4 == W - 4);   // j=4095 excluded entirely

    float acc = 0.0f;

    const float* p = base + (size_t)row0 * W + c4;
    float4 cur    = *(const float4*)p;
    float  curext = last_col ? 0.0f : p[4];

    // ---- 2-row unrolled mainloop ----
    int i = row0;
    const int pair_end = row0 + ((rend - row0) & ~1);
    for (; i < pair_end; i += 2) {
        const float* p1 = base + (size_t)(i + 1) * W + c4;
        const float* p2 = base + (size_t)(i + 2) * W + c4;
        float4 n1 = *(const float4*)p1;
        float4 n2 = *(const float4*)p2;
        float n1ext = last_col ? 0.0f : p1[4];
        float n2ext = last_col ? 0.0f : p2[4];

        tv_accum(acc, cur, curext, n1, last_col);
        tv_accum(acc, n1, n1ext, n2, last_col);

        cur = n2;
        curext = n2ext;
    }
    if (i < rend) {    // odd trailing row
        const float* p1 = base + (size_t)(i + 1) * W + c4;
        float4 n1 = *(const float4*)p1;
        tv_accum(acc, cur, curext, n1, last_col);
    }

    // ---- block reduction ----
    #pragma unroll
    for (int off = 16; off > 0; off >>= 1)
        acc += __shfl_down_sync(0xFFFFFFFFu, acc, off);

    __shared__ float warp_sums[THREADS / 32];
    __shared__ bool is_last;
    const int lane = threadIdx.x & 31;
    const int wid  = threadIdx.x >> 5;
    if (lane == 0) warp_sums[wid] = acc;
    __syncthreads();

    if (wid == 0) {
        float v = (lane < THREADS / 32) ? warp_sums[lane] : 0.0f;
        #pragma unroll
        for (int off = 4; off > 0; off >>= 1)
            v += __shfl_down_sync(0xFFFFFFFFu, v, off);
        if (lane == 0) {
            atomicAdd((double*)&g_acc_bits, (double)v);
            __threadfence();
            unsigned int ticket = atomicInc(&g_count, NUM_BLOCKS - 1);
            is_last = (ticket == NUM_BLOCKS - 1);   // wraps back to 0 for next replay
        }
    }
    __syncthreads();

    // Last block finalizes: read+reset accumulator, write sqrt.
    if (is_last && threadIdx.x == 0) {
        unsigned long long bits = atomicExch(&g_acc_bits, 0ull);
        double total = __longlong_as_double(bits);
        out[0] = (float)sqrt(total);
    }
}

extern "C" void kernel_launch(void* const* d_in, const int* in_sizes, int n_in,
                              void* d_out, int out_size) {
    const float* x = (const float*)d_in[0];
    float* out = (float*)d_out;

    dim3 grid(GRID_X, NGROUPS, CH);
    tv_fused_kernel<<<grid, THREADS>>>(x, out);
}